// round 2
// baseline (speedup 1.0000x reference)
#include <cuda_runtime.h>

// 3-level 2D Haar DWT, fused. x: (16,64,256,256) f32.
// Haar (len-2, stride-2) has zero overlap => each 8x8 input tile maps to an
// independent 3-level local pyramid. One thread per 8x8 tile, all in registers.
//
// Output layout (tree-leaves order of the reference's return tuple):
//   [ LL3 (NI,32,32) | LH3 | HL3 | HH3 | LH2 (NI,64,64) | HL2 | HH2
//     | LH1 (NI,128,128) | HL1 | HH1 ]
// where NI = 16*64 = 1024 images.

#define NI 1024

__device__ __forceinline__ void haar_quad(float a, float b, float c, float d,
                                          float& ll, float& lh, float& hl, float& hh) {
    // XLA conv = cross-correlation with filters:
    // ll=0.5[[1,1],[1,1]] lh=0.5[[1,1],[-1,-1]] hl=0.5[[1,-1],[1,-1]] hh=0.5[[1,-1],[-1,1]]
    float apb = a + b, cpd = c + d;
    float amb = a - b, cmd = c - d;
    ll = 0.5f * (apb + cpd);
    lh = 0.5f * (apb - cpd);
    hl = 0.5f * (amb + cmd);
    hh = 0.5f * (amb - cmd);
}

__global__ __launch_bounds__(256) void haar3_kernel(const float* __restrict__ x,
                                                    float* __restrict__ out) {
    const int T = blockIdx.x * blockDim.x + threadIdx.x;   // [0, NI*1024)
    const int img = T >> 10;
    const int idx = T & 1023;
    const int tr = idx >> 5;      // tile row (0..31)
    const int tc = idx & 31;      // tile col (0..31) -> consecutive lanes = consecutive cols

    const size_t S3 = 32 * 32;      // 1024
    const size_t S2 = 64 * 64;      // 4096
    const size_t S1 = 128 * 128;    // 16384

    const float* __restrict__ xin = x + (size_t)img * (256 * 256) + (size_t)tr * 8 * 256 + (size_t)tc * 8;

    // output band base offsets (elements)
    const size_t b_ll3 = 0;
    const size_t b_lh3 = (size_t)NI * S3;
    const size_t b_hl3 = 2 * (size_t)NI * S3;
    const size_t b_hh3 = 3 * (size_t)NI * S3;
    const size_t b_lh2 = 4 * (size_t)NI * S3;
    const size_t b_hl2 = b_lh2 + (size_t)NI * S2;
    const size_t b_hh2 = b_lh2 + 2 * (size_t)NI * S2;
    const size_t b_lh1 = b_lh2 + 3 * (size_t)NI * S2;
    const size_t b_hl1 = b_lh1 + (size_t)NI * S1;
    const size_t b_hh1 = b_lh1 + 2 * (size_t)NI * S1;

    // ---------------- level 1: 8x8 -> 4x4 ----------------
    float ll1[4][4];
    #pragma unroll
    for (int i = 0; i < 4; i++) {
        const float4 r0a = *(const float4*)(xin + (2 * i) * 256);
        const float4 r0b = *(const float4*)(xin + (2 * i) * 256 + 4);
        const float4 r1a = *(const float4*)(xin + (2 * i + 1) * 256);
        const float4 r1b = *(const float4*)(xin + (2 * i + 1) * 256 + 4);

        float4 lh, hl, hh;
        haar_quad(r0a.x, r0a.y, r1a.x, r1a.y, ll1[i][0], lh.x, hl.x, hh.x);
        haar_quad(r0a.z, r0a.w, r1a.z, r1a.w, ll1[i][1], lh.y, hl.y, hh.y);
        haar_quad(r0b.x, r0b.y, r1b.x, r1b.y, ll1[i][2], lh.z, hl.z, hh.z);
        haar_quad(r0b.z, r0b.w, r1b.z, r1b.w, ll1[i][3], lh.w, hl.w, hh.w);

        const size_t o1 = (size_t)img * S1 + (size_t)(tr * 4 + i) * 128 + (size_t)tc * 4;
        *(float4*)(out + b_lh1 + o1) = lh;
        *(float4*)(out + b_hl1 + o1) = hl;
        *(float4*)(out + b_hh1 + o1) = hh;
    }

    // ---------------- level 2: 4x4 -> 2x2 ----------------
    float ll2[2][2];
    #pragma unroll
    for (int i = 0; i < 2; i++) {
        float2 lh, hl, hh;
        haar_quad(ll1[2 * i][0], ll1[2 * i][1], ll1[2 * i + 1][0], ll1[2 * i + 1][1],
                  ll2[i][0], lh.x, hl.x, hh.x);
        haar_quad(ll1[2 * i][2], ll1[2 * i][3], ll1[2 * i + 1][2], ll1[2 * i + 1][3],
                  ll2[i][1], lh.y, hl.y, hh.y);

        const size_t o2 = (size_t)img * S2 + (size_t)(tr * 2 + i) * 64 + (size_t)tc * 2;
        *(float2*)(out + b_lh2 + o2) = lh;
        *(float2*)(out + b_hl2 + o2) = hl;
        *(float2*)(out + b_hh2 + o2) = hh;
    }

    // ---------------- level 3: 2x2 -> 1x1 ----------------
    float ll3, lh3, hl3, hh3;
    haar_quad(ll2[0][0], ll2[0][1], ll2[1][0], ll2[1][1], ll3, lh3, hl3, hh3);

    const size_t o3 = (size_t)img * S3 + (size_t)tr * 32 + (size_t)tc;
    out[b_ll3 + o3] = ll3;
    out[b_lh3 + o3] = lh3;
    out[b_hl3 + o3] = hl3;
    out[b_hh3 + o3] = hh3;
}

extern "C" void kernel_launch(void* const* d_in, const int* in_sizes, int n_in,
                              void* d_out, int out_size) {
    const float* x = (const float*)d_in[0];
    float* out = (float*)d_out;
    // NI*32*32 threads, one per 8x8 input tile
    const int total = NI * 32 * 32;
    haar3_kernel<<<total / 256, 256>>>(x, out);
}

// round 3
// speedup vs baseline: 1.0066x; 1.0066x over previous
#include <cuda_runtime.h>

// 3-level 2D Haar DWT, fused, streaming cache hints. x: (16,64,256,256) f32.
// Haar (len-2, stride-2) has zero overlap => each 8x8 input tile maps to an
// independent 3-level local pyramid. One thread per 8x8 tile, all in registers.
//
// R2 change: all global loads use __ldcs (evict-first) and all stores __stcs —
// every byte is single-touch, so keep the L2 a shallow streaming FIFO instead
// of letting 512MB thrash the 126MB L2 with normal-priority lines.
//
// Output layout (tree-leaves order of the reference's return tuple):
//   [ LL3 (NI,32,32) | LH3 | HL3 | HH3 | LH2 (NI,64,64) | HL2 | HH2
//     | LH1 (NI,128,128) | HL1 | HH1 ]
// where NI = 16*64 = 1024 images.

#define NI 1024

__device__ __forceinline__ void haar_quad(float a, float b, float c, float d,
                                          float& ll, float& lh, float& hl, float& hh) {
    // XLA conv = cross-correlation with filters:
    // ll=0.5[[1,1],[1,1]] lh=0.5[[1,1],[-1,-1]] hl=0.5[[1,-1],[1,-1]] hh=0.5[[1,-1],[-1,1]]
    float apb = a + b, cpd = c + d;
    float amb = a - b, cmd = c - d;
    ll = 0.5f * (apb + cpd);
    lh = 0.5f * (apb - cpd);
    hl = 0.5f * (amb + cmd);
    hh = 0.5f * (amb - cmd);
}

__global__ __launch_bounds__(256) void haar3_kernel(const float* __restrict__ x,
                                                    float* __restrict__ out) {
    const int T = blockIdx.x * blockDim.x + threadIdx.x;   // [0, NI*1024)
    const int img = T >> 10;
    const int idx = T & 1023;
    const int tr = idx >> 5;      // tile row (0..31)
    const int tc = idx & 31;      // tile col (0..31) -> consecutive lanes = consecutive cols

    const size_t S3 = 32 * 32;      // 1024
    const size_t S2 = 64 * 64;      // 4096
    const size_t S1 = 128 * 128;    // 16384

    const float* __restrict__ xin = x + (size_t)img * (256 * 256) + (size_t)tr * 8 * 256 + (size_t)tc * 8;

    // output band base offsets (elements)
    const size_t b_ll3 = 0;
    const size_t b_lh3 = (size_t)NI * S3;
    const size_t b_hl3 = 2 * (size_t)NI * S3;
    const size_t b_hh3 = 3 * (size_t)NI * S3;
    const size_t b_lh2 = 4 * (size_t)NI * S3;
    const size_t b_hl2 = b_lh2 + (size_t)NI * S2;
    const size_t b_hh2 = b_lh2 + 2 * (size_t)NI * S2;
    const size_t b_lh1 = b_lh2 + 3 * (size_t)NI * S2;
    const size_t b_hl1 = b_lh1 + (size_t)NI * S1;
    const size_t b_hh1 = b_lh1 + 2 * (size_t)NI * S1;

    // ---------------- level 1: 8x8 -> 4x4 ----------------
    float ll1[4][4];
    #pragma unroll
    for (int i = 0; i < 4; i++) {
        const float4 r0a = __ldcs((const float4*)(xin + (2 * i) * 256));
        const float4 r0b = __ldcs((const float4*)(xin + (2 * i) * 256 + 4));
        const float4 r1a = __ldcs((const float4*)(xin + (2 * i + 1) * 256));
        const float4 r1b = __ldcs((const float4*)(xin + (2 * i + 1) * 256 + 4));

        float4 lh, hl, hh;
        haar_quad(r0a.x, r0a.y, r1a.x, r1a.y, ll1[i][0], lh.x, hl.x, hh.x);
        haar_quad(r0a.z, r0a.w, r1a.z, r1a.w, ll1[i][1], lh.y, hl.y, hh.y);
        haar_quad(r0b.x, r0b.y, r1b.x, r1b.y, ll1[i][2], lh.z, hl.z, hh.z);
        haar_quad(r0b.z, r0b.w, r1b.z, r1b.w, ll1[i][3], lh.w, hl.w, hh.w);

        const size_t o1 = (size_t)img * S1 + (size_t)(tr * 4 + i) * 128 + (size_t)tc * 4;
        __stcs((float4*)(out + b_lh1 + o1), lh);
        __stcs((float4*)(out + b_hl1 + o1), hl);
        __stcs((float4*)(out + b_hh1 + o1), hh);
    }

    // ---------------- level 2: 4x4 -> 2x2 ----------------
    float ll2[2][2];
    #pragma unroll
    for (int i = 0; i < 2; i++) {
        float2 lh, hl, hh;
        haar_quad(ll1[2 * i][0], ll1[2 * i][1], ll1[2 * i + 1][0], ll1[2 * i + 1][1],
                  ll2[i][0], lh.x, hl.x, hh.x);
        haar_quad(ll1[2 * i][2], ll1[2 * i][3], ll1[2 * i + 1][2], ll1[2 * i + 1][3],
                  ll2[i][1], lh.y, hl.y, hh.y);

        const size_t o2 = (size_t)img * S2 + (size_t)(tr * 2 + i) * 64 + (size_t)tc * 2;
        __stcs((float2*)(out + b_lh2 + o2), lh);
        __stcs((float2*)(out + b_hl2 + o2), hl);
        __stcs((float2*)(out + b_hh2 + o2), hh);
    }

    // ---------------- level 3: 2x2 -> 1x1 ----------------
    float ll3, lh3, hl3, hh3;
    haar_quad(ll2[0][0], ll2[0][1], ll2[1][0], ll2[1][1], ll3, lh3, hl3, hh3);

    const size_t o3 = (size_t)img * S3 + (size_t)tr * 32 + (size_t)tc;
    __stcs(out + b_ll3 + o3, ll3);
    __stcs(out + b_lh3 + o3, lh3);
    __stcs(out + b_hl3 + o3, hl3);
    __stcs(out + b_hh3 + o3, hh3);
}

extern "C" void kernel_launch(void* const* d_in, const int* in_sizes, int n_in,
                              void* d_out, int out_size) {
    const float* x = (const float*)d_in[0];
    float* out = (float*)d_out;
    // NI*32*32 threads, one per 8x8 input tile
    const int total = NI * 32 * 32;
    haar3_kernel<<<total / 256, 256>>>(x, out);
}

// round 6
// speedup vs baseline: 1.0070x; 1.0004x over previous
#include <cuda_runtime.h>

// 3-level 2D Haar DWT, fused. x: (16,64,256,256) f32.
// One thread per 8x8 input tile; 3-level local pyramid entirely in registers.
//
// R3 change: front-batch ALL 16 LDG.128 loads before any compute/store
// (MLP_p1 = 16 per thread). Registers rise to ~96 -> 2 blocks/SM, but the
// uninterrupted load burst improves L1tex wavefront pipelining and DRAM read
// scheduling. Streaming store hints retained.
//
// Output layout (tree-leaves order of the reference's return tuple):
//   [ LL3 (NI,32,32) | LH3 | HL3 | HH3 | LH2 (NI,64,64) | HL2 | HH2
//     | LH1 (NI,128,128) | HL1 | HH1 ]   with NI = 16*64 = 1024 images.

#define NI 1024

__device__ __forceinline__ void haar_quad(float a, float b, float c, float d,
                                          float& ll, float& lh, float& hl, float& hh) {
    float apb = a + b, cpd = c + d;
    float amb = a - b, cmd = c - d;
    ll = 0.5f * (apb + cpd);
    lh = 0.5f * (apb - cpd);
    hl = 0.5f * (amb + cmd);
    hh = 0.5f * (amb - cmd);
}

__global__ __launch_bounds__(256) void haar3_kernel(const float* __restrict__ x,
                                                    float* __restrict__ out) {
    const int T = blockIdx.x * blockDim.x + threadIdx.x;   // [0, NI*1024)
    const int img = T >> 10;
    const int idx = T & 1023;
    const int tr = idx >> 5;      // tile row (0..31)
    const int tc = idx & 31;      // tile col (0..31) -> consecutive lanes = consecutive cols

    const size_t S3 = 32 * 32;
    const size_t S2 = 64 * 64;
    const size_t S1 = 128 * 128;

    const float* __restrict__ xin =
        x + (size_t)img * (256 * 256) + (size_t)tr * 8 * 256 + (size_t)tc * 8;

    // output band base offsets (elements)
    const size_t b_ll3 = 0;
    const size_t b_lh3 = (size_t)NI * S3;
    const size_t b_hl3 = 2 * (size_t)NI * S3;
    const size_t b_hh3 = 3 * (size_t)NI * S3;
    const size_t b_lh2 = 4 * (size_t)NI * S3;
    const size_t b_hl2 = b_lh2 + (size_t)NI * S2;
    const size_t b_hh2 = b_lh2 + 2 * (size_t)NI * S2;
    const size_t b_lh1 = b_lh2 + 3 * (size_t)NI * S2;
    const size_t b_hl1 = b_lh1 + (size_t)NI * S1;
    const size_t b_hh1 = b_lh1 + 2 * (size_t)NI * S1;

    // ---------------- front-batched loads: all 16 LDG.128 ----------------
    float4 r[8][2];                  // r[row][half]: 8 image rows x 32B
    #pragma unroll
    for (int row = 0; row < 8; row++) {
        r[row][0] = __ldcs((const float4*)(xin + row * 256));
        r[row][1] = __ldcs((const float4*)(xin + row * 256 + 4));
    }

    // ---------------- level 1: 8x8 -> 4x4 ----------------
    float ll1[4][4];
    #pragma unroll
    for (int i = 0; i < 4; i++) {
        const float4 r0a = r[2 * i][0],     r0b = r[2 * i][1];
        const float4 r1a = r[2 * i + 1][0], r1b = r[2 * i + 1][1];

        float4 lh, hl, hh;
        haar_quad(r0a.x, r0a.y, r1a.x, r1a.y, ll1[i][0], lh.x, hl.x, hh.x);
        haar_quad(r0a.z, r0a.w, r1a.z, r1a.w, ll1[i][1], lh.y, hl.y, hh.y);
        haar_quad(r0b.x, r0b.y, r1b.x, r1b.y, ll1[i][2], lh.z, hl.z, hh.z);
        haar_quad(r0b.z, r0b.w, r1b.z, r1b.w, ll1[i][3], lh.w, hl.w, hh.w);

        const size_t o1 = (size_t)img * S1 + (size_t)(tr * 4 + i) * 128 + (size_t)tc * 4;
        __stcs((float4*)(out + b_lh1 + o1), lh);
        __stcs((float4*)(out + b_hl1 + o1), hl);
        __stcs((float4*)(out + b_hh1 + o1), hh);
    }

    // ---------------- level 2: 4x4 -> 2x2 ----------------
    float ll2[2][2];
    #pragma unroll
    for (int i = 0; i < 2; i++) {
        float2 lh, hl, hh;
        haar_quad(ll1[2 * i][0], ll1[2 * i][1], ll1[2 * i + 1][0], ll1[2 * i + 1][1],
                  ll2[i][0], lh.x, hl.x, hh.x);
        haar_quad(ll1[2 * i][2], ll1[2 * i][3], ll1[2 * i + 1][2], ll1[2 * i + 1][3],
                  ll2[i][1], lh.y, hl.y, hh.y);

        const size_t o2 = (size_t)img * S2 + (size_t)(tr * 2 + i) * 64 + (size_t)tc * 2;
        __stcs((float2*)(out + b_lh2 + o2), lh);
        __stcs((float2*)(out + b_hl2 + o2), hl);
        __stcs((float2*)(out + b_hh2 + o2), hh);
    }

    // ---------------- level 3: 2x2 -> 1x1 ----------------
    float ll3, lh3, hl3, hh3;
    haar_quad(ll2[0][0], ll2[0][1], ll2[1][0], ll2[1][1], ll3, lh3, hl3, hh3);

    const size_t o3 = (size_t)img * S3 + (size_t)tr * 32 + (size_t)tc;
    __stcs(out + b_ll3 + o3, ll3);
    __stcs(out + b_lh3 + o3, lh3);
    __stcs(out + b_hl3 + o3, hl3);
    __stcs(out + b_hh3 + o3, hh3);
}

extern "C" void kernel_launch(void* const* d_in, const int* in_sizes, int n_in,
                              void* d_out, int out_size) {
    const float* x = (const float*)d_in[0];
    float* out = (float*)d_out;
    const int total = NI * 32 * 32;   // one thread per 8x8 tile
    haar3_kernel<<<total / 256, 256>>>(x, out);
}